// round 5
// baseline (speedup 1.0000x reference)
#include <cuda_runtime.h>
#include <cuda_fp16.h>
#include <math.h>

#define N_NODES 50000
#define N_EDGES 800000
#define E_TOT   850000          // edges + self loops
#define IN_DIM  128
#define HID     64
#define HEADS   4
#define F1      256             // HEADS*HID
#define OUT_DIM 16
#define N_GRAPHS 500
#define NEG_SLOPE 0.2f

// ---------------- device scratch (static, no runtime alloc) ----------------
__device__ __align__(16) __half g_h[N_NODES * F1];     // post-GEMM features [N,256], fp16
__device__ __align__(16) float g_hpost[N_NODES * HID]; // post-attention features [N,64]
__device__ __align__(16) float g_as[N_NODES * HEADS];
__device__ __align__(16) float g_ad[N_NODES * HEADS];
__device__ int   g_count[N_NODES];
__device__ int   g_rowptr[N_NODES + 1];
__device__ int   g_cursor[N_NODES];
__device__ int   g_col[E_TOT];             // src index per CSR slot
__device__ int   g_chunksum[64];
__device__ int   g_chunkoff[64];

// ---------------- packed f32x2 helpers ----------------
#define FMA_F32X2(d, a, b) \
    asm("fma.rn.f32x2 %0, %1, %2, %0;" : "+l"(d) : "l"(a), "l"(b))
#define PACK_DUP_F32X2(d, f) \
    asm("mov.b64 %0, {%1, %1};" : "=l"(d) : "f"(f))

// ============================================================================
// CSR build  (edge_index is int32: row 0 = src, row 1 = dst)
// ============================================================================
__global__ void k_zero_count() {
    int i = blockIdx.x * blockDim.x + threadIdx.x;
    if (i < N_NODES) g_count[i] = 0;
}

__global__ void k_hist(const int* __restrict__ ei) {
    int e = blockIdx.x * blockDim.x + threadIdx.x;
    if (e >= E_TOT) return;
    int dst = (e < N_EDGES) ? ei[N_EDGES + e] : (e - N_EDGES);
    atomicAdd(&g_count[dst], 1);
}

__global__ void k_scan1() {
    __shared__ int sh[1024];
    int tid = threadIdx.x;
    int i = blockIdx.x * 1024 + tid;
    int v = (i < N_NODES) ? g_count[i] : 0;
    sh[tid] = v;
    __syncthreads();
#pragma unroll
    for (int off = 1; off < 1024; off <<= 1) {
        int t = (tid >= off) ? sh[tid - off] : 0;
        __syncthreads();
        sh[tid] += t;
        __syncthreads();
    }
    if (i < N_NODES) g_rowptr[i + 1] = sh[tid];   // chunk-local inclusive
    if (tid == 1023) g_chunksum[blockIdx.x] = sh[1023];
}

__global__ void k_scan2(int nch) {
    __shared__ int s[64];
    int tid = threadIdx.x;
    int v = (tid < nch) ? g_chunksum[tid] : 0;
    s[tid] = v;
    __syncthreads();
#pragma unroll
    for (int off = 1; off < 64; off <<= 1) {
        int t = (tid >= off) ? s[tid - off] : 0;
        __syncthreads();
        s[tid] += t;
        __syncthreads();
    }
    if (tid < nch) g_chunkoff[tid] = s[tid] - v;  // exclusive
}

// scan3 + cursor init fused
__global__ void k_scan3() {
    int tid = threadIdx.x;
    int i = blockIdx.x * 1024 + tid;
    if (i < N_NODES) {
        int v = g_rowptr[i + 1] + g_chunkoff[blockIdx.x];
        g_rowptr[i + 1] = v;
    }
    if (blockIdx.x == 0 && tid == 0) g_rowptr[0] = 0;
}

__global__ void k_cursor_scatter_init() {
    int i = blockIdx.x * blockDim.x + threadIdx.x;
    if (i < N_NODES) g_cursor[i] = g_rowptr[i];
}

__global__ void k_scatter(const int* __restrict__ ei) {
    int e = blockIdx.x * blockDim.x + threadIdx.x;
    if (e >= E_TOT) return;
    int src, dst;
    if (e < N_EDGES) {
        src = ei[e];
        dst = ei[N_EDGES + e];
    } else {
        src = dst = e - N_EDGES;
    }
    int p = atomicAdd(&g_cursor[dst], 1);
    g_col[p] = src;
}

// ============================================================================
// GEMM: g_h[M,256](fp16) = A[M,K](fp32) @ W[K,256](fp32), fp32 accumulate.
// Fused epilogue: g_as[n,h], g_ad[n,h] from fp32 accumulators.
// BM=64, BN=128 (grid.y halves), Kc=64 chunks, TM=4, TN=8, 256 threads.
// ============================================================================
template <int K, bool USE_EXT>
__global__ __launch_bounds__(256) void k_gemm256(
    const float* __restrict__ Aext, const float* __restrict__ W,
    const float* __restrict__ a_src, const float* __restrict__ a_dst)
{
    __shared__ float As[64][64];     // 16 KB, [row][k]
    __shared__ float Bs[64][128];    // 32 KB, [k][col]

    const float* A = USE_EXT ? Aext : (const float*)g_hpost;

    int tid = threadIdx.x;
    int row0 = blockIdx.x * 64;
    int ncol0 = blockIdx.y * 128;

    int rg = tid >> 4;      // row group 0..15 -> rows rg*4..rg*4+3
    int cg = tid & 15;      // col group 0..15 -> cols cg*8..cg*8+7

    unsigned long long acc[4][4];
#pragma unroll
    for (int i = 0; i < 4; i++)
#pragma unroll
        for (int j = 0; j < 4; j++) acc[i][j] = 0ull;

#pragma unroll
    for (int kc = 0; kc < K; kc += 64) {
#pragma unroll
        for (int it = 0; it < 4; it++) {
            int idx = tid + it * 256;          // 1024 float4 slots
            int r = idx >> 4, c4 = idx & 15;
            int row = row0 + r;
            float4 a = (row < N_NODES)
                ? *(const float4*)(A + (long)row * K + kc + c4 * 4)
                : make_float4(0.f, 0.f, 0.f, 0.f);
            *(float4*)(&As[r][c4 * 4]) = a;
        }
#pragma unroll
        for (int it = 0; it < 8; it++) {
            int idx = tid + it * 256;          // 2048 float4 slots
            int k = idx >> 5, j4 = idx & 31;
            float4 w = *(const float4*)(W + (long)(kc + k) * 256 + ncol0 + j4 * 4);
            *(float4*)(&Bs[k][j4 * 4]) = w;
        }
        __syncthreads();

#pragma unroll
        for (int k4 = 0; k4 < 64; k4 += 4) {
            float4 a4[4];
#pragma unroll
            for (int i = 0; i < 4; i++)
                a4[i] = *(const float4*)(&As[rg * 4 + i][k4]);
#pragma unroll
            for (int kk = 0; kk < 4; kk++) {
                union { float4 f; unsigned long long u[2]; } ua, ub;
                const float* brow = &Bs[k4 + kk][cg * 8];
                ua.f = *(const float4*)(brow);
                ub.f = *(const float4*)(brow + 4);
                unsigned long long b0 = ua.u[0], b1 = ua.u[1];
                unsigned long long b2 = ub.u[0], b3 = ub.u[1];
#pragma unroll
                for (int i = 0; i < 4; i++) {
                    float a = (kk == 0) ? a4[i].x : (kk == 1) ? a4[i].y
                            : (kk == 2) ? a4[i].z : a4[i].w;
                    unsigned long long ap;
                    PACK_DUP_F32X2(ap, a);
                    FMA_F32X2(acc[i][0], ap, b0);
                    FMA_F32X2(acc[i][1], ap, b1);
                    FMA_F32X2(acc[i][2], ap, b2);
                    FMA_F32X2(acc[i][3], ap, b3);
                }
            }
        }
        __syncthreads();
    }

    // epilogue: store fp16 h, compute fused as/ad
    int c0 = ncol0 + cg * 8;                 // global col of this thread's 8
    float4 av0 = *(const float4*)(a_src + c0);
    float4 av1 = *(const float4*)(a_src + c0 + 4);
    float4 dv0 = *(const float4*)(a_dst + c0);
    float4 dv1 = *(const float4*)(a_dst + c0 + 4);
    int head = (c0 >> 6);                    // global head id of these 8 cols

#pragma unroll
    for (int i = 0; i < 4; i++) {
        int row = row0 + rg * 4 + i;
        float2 f0 = *(float2*)&acc[i][0];
        float2 f1 = *(float2*)&acc[i][1];
        float2 f2 = *(float2*)&acc[i][2];
        float2 f3 = *(float2*)&acc[i][3];

        if (row < N_NODES) {
            __half* cp = g_h + (long)row * 256 + c0;
            __half2 q[4];
            q[0] = __float22half2_rn(f0);
            q[1] = __float22half2_rn(f1);
            q[2] = __float22half2_rn(f2);
            q[3] = __float22half2_rn(f3);
            *(uint4*)cp = *(uint4*)q;
        }

        float ps = f0.x*av0.x + f0.y*av0.y + f1.x*av0.z + f1.y*av0.w
                 + f2.x*av1.x + f2.y*av1.y + f3.x*av1.z + f3.y*av1.w;
        float pd = f0.x*dv0.x + f0.y*dv0.y + f1.x*dv0.z + f1.y*dv0.w
                 + f2.x*dv1.x + f2.y*dv1.y + f3.x*dv1.z + f3.y*dv1.w;
        // reduce across 8-lane cg groups (cg 0..7 and 8..15 are contiguous lanes)
#pragma unroll
        for (int off = 1; off < 8; off <<= 1) {
            ps += __shfl_xor_sync(0xFFFFFFFF, ps, off);
            pd += __shfl_xor_sync(0xFFFFFFFF, pd, off);
        }
        if ((cg & 7) == 0 && row < N_NODES) {
            g_as[row * HEADS + head] = ps;
            g_ad[row * HEADS + head] = pd;
        }
    }
}

// ============================================================================
// GAT attention: online softmax (fused max+sum pass) + aggregation + head-mean
// + bias + relu.  One warp per dst node.
// ============================================================================
__device__ __forceinline__ float lrelu(float v) {
    return v > 0.f ? v : NEG_SLOPE * v;
}

__global__ __launch_bounds__(256) void k_gat_attn(
    const float* __restrict__ bias)
{
    int n = (blockIdx.x * blockDim.x + threadIdx.x) >> 5;
    int lane = threadIdx.x & 31;
    if (n >= N_NODES) return;

    int beg = g_rowptr[n], end = g_rowptr[n + 1];
    float4 adv = *(const float4*)(g_ad + n * 4);
    float ad0 = adv.x, ad1 = adv.y, ad2 = adv.z, ad3 = adv.w;

    // fused pass: online (max, rescaled sum) per head  (-1e30 sentinel, finite)
    float mx0 = -1e30f, mx1 = -1e30f, mx2 = -1e30f, mx3 = -1e30f;
    float se0 = 0.f, se1 = 0.f, se2 = 0.f, se3 = 0.f;
    for (int e = beg + lane; e < end; e += 32) {
        int s = g_col[e];
        float4 av = *(const float4*)(g_as + s * 4);
        float e0 = lrelu(av.x + ad0), e1 = lrelu(av.y + ad1);
        float e2 = lrelu(av.z + ad2), e3 = lrelu(av.w + ad3);
        float m;
        m = fmaxf(mx0, e0); se0 = se0 * __expf(mx0 - m) + __expf(e0 - m); mx0 = m;
        m = fmaxf(mx1, e1); se1 = se1 * __expf(mx1 - m) + __expf(e1 - m); mx1 = m;
        m = fmaxf(mx2, e2); se2 = se2 * __expf(mx2 - m) + __expf(e2 - m); mx2 = m;
        m = fmaxf(mx3, e3); se3 = se3 * __expf(mx3 - m) + __expf(e3 - m); mx3 = m;
    }
    // warp-combine (max, sum) pairs
#pragma unroll
    for (int off = 16; off >= 1; off >>= 1) {
        float m2, s2, mm;
        m2 = __shfl_xor_sync(0xFFFFFFFF, mx0, off); s2 = __shfl_xor_sync(0xFFFFFFFF, se0, off);
        mm = fmaxf(mx0, m2); se0 = se0 * __expf(mx0 - mm) + s2 * __expf(m2 - mm); mx0 = mm;
        m2 = __shfl_xor_sync(0xFFFFFFFF, mx1, off); s2 = __shfl_xor_sync(0xFFFFFFFF, se1, off);
        mm = fmaxf(mx1, m2); se1 = se1 * __expf(mx1 - mm) + s2 * __expf(m2 - mm); mx1 = mm;
        m2 = __shfl_xor_sync(0xFFFFFFFF, mx2, off); s2 = __shfl_xor_sync(0xFFFFFFFF, se2, off);
        mm = fmaxf(mx2, m2); se2 = se2 * __expf(mx2 - mm) + s2 * __expf(m2 - mm); mx2 = mm;
        m2 = __shfl_xor_sync(0xFFFFFFFF, mx3, off); s2 = __shfl_xor_sync(0xFFFFFFFF, se3, off);
        mm = fmaxf(mx3, m2); se3 = se3 * __expf(mx3 - mm) + s2 * __expf(m2 - mm); mx3 = mm;
    }

    // aggregation pass: lane owns flat features lane*8..lane*8+7
    int h0 = lane >> 3;
    float myad = (h0 == 0) ? ad0 : (h0 == 1) ? ad1 : (h0 == 2) ? ad2 : ad3;
    float mymx = (h0 == 0) ? mx0 : (h0 == 1) ? mx1 : (h0 == 2) ? mx2 : mx3;
    float myinv = 1.f / ((h0 == 0) ? se0 : (h0 == 1) ? se1 : (h0 == 2) ? se2 : se3);
    int k0 = lane * 8;

    float acc[8];
#pragma unroll
    for (int k = 0; k < 8; k++) acc[k] = 0.f;

    for (int e = beg; e < end; e++) {
        int s = g_col[e];                         // uniform -> broadcast load
        float myas = g_as[s * 4 + h0];
        float alpha = __expf(lrelu(myas + myad) - mymx) * myinv;
        const __half* hp = g_h + (long)s * F1 + k0;
        uint4 raw = *(const uint4*)hp;            // 8 halves
        __half2* ph = (__half2*)&raw;
        float2 f0 = __half22float2(ph[0]);
        float2 f1 = __half22float2(ph[1]);
        float2 f2 = __half22float2(ph[2]);
        float2 f3 = __half22float2(ph[3]);
        acc[0] += alpha * f0.x; acc[1] += alpha * f0.y;
        acc[2] += alpha * f1.x; acc[3] += alpha * f1.y;
        acc[4] += alpha * f2.x; acc[5] += alpha * f2.y;
        acc[6] += alpha * f3.x; acc[7] += alpha * f3.y;
    }

    // head mean: sum lanes {l, l^8, l^16, l^24} (same within-head dim slot)
#pragma unroll
    for (int k = 0; k < 8; k++) {
        acc[k] += __shfl_xor_sync(0xFFFFFFFF, acc[k], 8);
        acc[k] += __shfl_xor_sync(0xFFFFFFFF, acc[k], 16);
    }
    if (lane < 8) {
        float* op = g_hpost + (long)n * HID + lane * 8;
#pragma unroll
        for (int k = 0; k < 8; k++) {
            float v = acc[k] * 0.25f + bias[lane * 8 + k];
            op[k] = v > 0.f ? v : 0.f;
        }
    }
}

// ============================================================================
// pool (segment mean over sorted batch) + FC  (one block per graph, 64 thr)
// ============================================================================
__device__ __forceinline__ int lowerb(const int* b, int n, int v) {
    int lo = 0, hi = n;
    while (lo < hi) {
        int m = (lo + hi) >> 1;
        if (b[m] < v) lo = m + 1; else hi = m;
    }
    return lo;
}

__global__ __launch_bounds__(64) void k_pool_fc(
    const int* __restrict__ batch,
    const float* __restrict__ fcW, const float* __restrict__ fcb,
    float* __restrict__ out)
{
    int g = blockIdx.x;
    int d = threadIdx.x;
    int lo = lowerb(batch, N_NODES, g);
    int hi = lowerb(batch, N_NODES, g + 1);
    float acc = 0.f;
    for (int i = lo; i < hi; i++) acc += g_hpost[(long)i * HID + d];
    int cnt = hi - lo;
    float inv = 1.f / (float)(cnt > 0 ? cnt : 1);
    __shared__ float sp[HID];
    sp[d] = acc * inv;
    __syncthreads();
    if (d < OUT_DIM) {
        float o = fcb[d];
#pragma unroll
        for (int k = 0; k < HID; k++) o += sp[k] * fcW[k * OUT_DIM + d];
        out[g * OUT_DIM + d] = o;
    }
}

// ============================================================================
// launcher — kernel launches ONLY (graph-capture safe)
// ============================================================================
extern "C" void kernel_launch(void* const* d_in, const int* in_sizes, int n_in,
                              void* d_out, int out_size)
{
    const float* x     = (const float*)d_in[0];
    const int*   ei    = (const int*)d_in[1];     // int32 (JAX x64 disabled)
    const int*   batch = (const int*)d_in[2];     // int32
    const float* W1    = (const float*)d_in[3];
    const float* a1s   = (const float*)d_in[4];
    const float* a1d   = (const float*)d_in[5];
    const float* b1    = (const float*)d_in[6];
    const float* W2    = (const float*)d_in[7];
    const float* a2s   = (const float*)d_in[8];
    const float* a2d   = (const float*)d_in[9];
    const float* b2    = (const float*)d_in[10];
    const float* fcW   = (const float*)d_in[11];
    const float* fcb   = (const float*)d_in[12];
    float*       out   = (float*)d_out;

    const int NCH = (N_NODES + 1023) / 1024;   // 49
    dim3 ggrid((N_NODES + 63) / 64, 2);

    // positions 1-3: CSR front half
    k_zero_count<<<(N_NODES + 255) / 256, 256>>>();
    k_hist<<<(E_TOT + 255) / 256, 256>>>(ei);
    k_scan1<<<NCH, 1024>>>();
    // position 4: big GEMM (CSR-independent) — lands in the ncu capture window
    k_gemm256<128, true><<<ggrid, 256>>>(x, W1, a1s, a1d);
    // CSR back half
    k_scan2<<<1, 64>>>(NCH);
    k_scan3<<<NCH, 1024>>>();
    k_cursor_scatter_init<<<(N_NODES + 255) / 256, 256>>>();
    k_scatter<<<(E_TOT + 255) / 256, 256>>>(ei);

    // layer 1 attention
    k_gat_attn<<<(N_NODES + 7) / 8, 256>>>(b1);

    // layer 2
    k_gemm256<64, false><<<ggrid, 256>>>(nullptr, W2, a2s, a2d);
    k_gat_attn<<<(N_NODES + 7) / 8, 256>>>(b2);

    // pool + fc
    k_pool_fc<<<N_GRAPHS, 64>>>(batch, fcW, fcb, out);
}

// round 6
// speedup vs baseline: 1.5311x; 1.5311x over previous
#include <cuda_runtime.h>
#include <cuda_fp16.h>
#include <math.h>

#define N_NODES 50000
#define N_EDGES 800000
#define E_TOT   850000          // edges + self loops
#define IN_DIM  128
#define HID     64
#define HEADS   4
#define F1      256             // HEADS*HID
#define OUT_DIM 16
#define N_GRAPHS 500
#define NEG_SLOPE 0.2f

// ---------------- device scratch (static, no runtime alloc) ----------------
__device__ __align__(16) __half g_xh[N_NODES * IN_DIM];   // x in fp16
__device__ __align__(16) __half g_w1h[IN_DIM * F1];       // W1 fp16
__device__ __align__(16) __half g_w2h[HID * F1];          // W2 fp16
__device__ __align__(16) __half g_h[N_NODES * F1];        // post-GEMM features, fp16
__device__ __align__(16) __half g_hpost[N_NODES * HID];   // post-attention, fp16
__device__ __align__(16) float g_as[N_NODES * HEADS];
__device__ __align__(16) float g_ad[N_NODES * HEADS];
__device__ int   g_count[N_NODES];
__device__ int   g_rowptr[N_NODES + 1];
__device__ int   g_cursor[N_NODES];
__device__ int   g_col[E_TOT];
__device__ int   g_chunksum[64];
__device__ int   g_chunkoff[64];

// ---------------- mma helpers ----------------
__device__ __forceinline__ unsigned su32(const void* p) {
    return (unsigned)__cvta_generic_to_shared(p);
}
__device__ __forceinline__ void ldsm_x4(unsigned* r, unsigned addr) {
    asm volatile("ldmatrix.sync.aligned.m8n8.x4.shared.b16 {%0,%1,%2,%3}, [%4];"
        : "=r"(r[0]), "=r"(r[1]), "=r"(r[2]), "=r"(r[3]) : "r"(addr));
}
__device__ __forceinline__ void ldsm_x4_t(unsigned* r, unsigned addr) {
    asm volatile("ldmatrix.sync.aligned.m8n8.x4.trans.shared.b16 {%0,%1,%2,%3}, [%4];"
        : "=r"(r[0]), "=r"(r[1]), "=r"(r[2]), "=r"(r[3]) : "r"(addr));
}
__device__ __forceinline__ void mma16816(float* d, const unsigned* a, const unsigned* b) {
    asm volatile("mma.sync.aligned.m16n8k16.row.col.f32.f16.f16.f32 "
        "{%0,%1,%2,%3}, {%4,%5,%6,%7}, {%8,%9}, {%0,%1,%2,%3};"
        : "+f"(d[0]), "+f"(d[1]), "+f"(d[2]), "+f"(d[3])
        : "r"(a[0]), "r"(a[1]), "r"(a[2]), "r"(a[3]), "r"(b[0]), "r"(b[1]));
}

// ============================================================================
// fp32 -> fp16 conversions
// ============================================================================
__global__ void k_cvt_x(const float* __restrict__ x) {
    int i = blockIdx.x * blockDim.x + threadIdx.x;   // float4 index
    const int total = N_NODES * IN_DIM / 4;
    if (i >= total) return;
    float4 v = *(const float4*)(x + (long)i * 4);
    __half2 h0 = __floats2half2_rn(v.x, v.y);
    __half2 h1 = __floats2half2_rn(v.z, v.w);
    __half2* p = (__half2*)(g_xh + (long)i * 4);
    p[0] = h0; p[1] = h1;
}

__global__ void k_cvt_w(const float* __restrict__ W1, const float* __restrict__ W2) {
    int i = blockIdx.x * blockDim.x + threadIdx.x;
    const int n1 = IN_DIM * F1;         // 32768
    const int n2 = HID * F1;            // 16384
    if (i < n1) g_w1h[i] = __float2half_rn(W1[i]);
    else if (i < n1 + n2) g_w2h[i - n1] = __float2half_rn(W2[i - n1]);
}

// ============================================================================
// CSR build  (edge_index is int32: row 0 = src, row 1 = dst)
// ============================================================================
__global__ void k_zero_count() {
    int i = blockIdx.x * blockDim.x + threadIdx.x;
    if (i < N_NODES) g_count[i] = 0;
}

__global__ void k_hist(const int* __restrict__ ei) {
    int e = blockIdx.x * blockDim.x + threadIdx.x;
    if (e >= E_TOT) return;
    int dst = (e < N_EDGES) ? ei[N_EDGES + e] : (e - N_EDGES);
    atomicAdd(&g_count[dst], 1);
}

__global__ void k_scan1() {
    __shared__ int sh[1024];
    int tid = threadIdx.x;
    int i = blockIdx.x * 1024 + tid;
    int v = (i < N_NODES) ? g_count[i] : 0;
    sh[tid] = v;
    __syncthreads();
#pragma unroll
    for (int off = 1; off < 1024; off <<= 1) {
        int t = (tid >= off) ? sh[tid - off] : 0;
        __syncthreads();
        sh[tid] += t;
        __syncthreads();
    }
    if (i < N_NODES) g_rowptr[i + 1] = sh[tid];
    if (tid == 1023) g_chunksum[blockIdx.x] = sh[1023];
}

__global__ void k_scan2(int nch) {
    __shared__ int s[64];
    int tid = threadIdx.x;
    int v = (tid < nch) ? g_chunksum[tid] : 0;
    s[tid] = v;
    __syncthreads();
#pragma unroll
    for (int off = 1; off < 64; off <<= 1) {
        int t = (tid >= off) ? s[tid - off] : 0;
        __syncthreads();
        s[tid] += t;
        __syncthreads();
    }
    if (tid < nch) g_chunkoff[tid] = s[tid] - v;
}

__global__ void k_scan3() {
    int tid = threadIdx.x;
    int i = blockIdx.x * 1024 + tid;
    if (i < N_NODES) g_rowptr[i + 1] += g_chunkoff[blockIdx.x];
    if (blockIdx.x == 0 && tid == 0) g_rowptr[0] = 0;
}

__global__ void k_cursor_init() {
    int i = blockIdx.x * blockDim.x + threadIdx.x;
    if (i < N_NODES) g_cursor[i] = g_rowptr[i];
}

__global__ void k_scatter(const int* __restrict__ ei) {
    int e = blockIdx.x * blockDim.x + threadIdx.x;
    if (e >= E_TOT) return;
    int src, dst;
    if (e < N_EDGES) {
        src = ei[e];
        dst = ei[N_EDGES + e];
    } else {
        src = dst = e - N_EDGES;
    }
    int p = atomicAdd(&g_cursor[dst], 1);
    g_col[p] = src;
}

// ============================================================================
// HMMA GEMM: g_h[M,256](fp16) = A[M,K](fp16) @ W[K,256](fp16), fp32 acc.
// Fused epilogue: g_as/g_ad from fp32 accumulators.
// BM=128, BN=128 (grid.y=2), BK=32. 256 threads = 8 warps (4x2), warp=32x64.
// Each warp's 64 cols = exactly one head.
// ============================================================================
#define SA 40    // As row stride (halves): 80B -> conflict-free ldmatrix
#define SB 136   // Bs row stride (halves): 272B -> conflict-free ldmatrix.trans

template <int K, bool USE_X>
__global__ __launch_bounds__(256) void k_gemm_hmma(
    const float* __restrict__ a_src, const float* __restrict__ a_dst)
{
    __shared__ __half As[128][SA];   // 10.2 KB
    __shared__ __half Bs[32][SB];    // 8.7 KB

    const __half* A = USE_X ? g_xh : g_hpost;
    const __half* W = USE_X ? g_w1h : g_w2h;

    int tid = threadIdx.x;
    int lane = tid & 31, wid = tid >> 5;
    int wm = wid >> 1, wn = wid & 1;
    int row0 = blockIdx.x * 128;
    int ncol0 = blockIdx.y * 128;

    float acc[2][8][4];
#pragma unroll
    for (int mi = 0; mi < 2; mi++)
#pragma unroll
        for (int ni = 0; ni < 8; ni++)
#pragma unroll
            for (int q = 0; q < 4; q++) acc[mi][ni][q] = 0.f;

#pragma unroll
    for (int kc = 0; kc < K; kc += 32) {
        // A tile: 128 rows x 32 halves (uint4 = 8 halves; 4 per row)
#pragma unroll
        for (int it = 0; it < 2; it++) {
            int idx = tid + it * 256;       // 0..511
            int r = idx >> 2, c = idx & 3;
            int row = row0 + r;
            uint4 v = make_uint4(0u, 0u, 0u, 0u);
            if (row < N_NODES) v = *(const uint4*)(A + (long)row * K + kc + c * 8);
            *(uint4*)(&As[r][c * 8]) = v;
        }
        // B tile: 32 rows x 128 halves (16 uint4 per row)
#pragma unroll
        for (int it = 0; it < 2; it++) {
            int idx = tid + it * 256;       // 0..511
            int k = idx >> 4, c = idx & 15;
            uint4 v = *(const uint4*)(W + (long)(kc + k) * 256 + ncol0 + c * 8);
            *(uint4*)(&Bs[k][c * 8]) = v;
        }
        __syncthreads();

#pragma unroll
        for (int ks = 0; ks < 32; ks += 16) {
            unsigned af[2][4];
#pragma unroll
            for (int mi = 0; mi < 2; mi++) {
                unsigned ad = su32(&As[wm * 32 + mi * 16 + (lane & 15)][ks + (lane >> 4) * 8]);
                ldsm_x4(af[mi], ad);
            }
            unsigned bf[4][4];   // bf[j]: regs 0,1 = n-tile 2j; regs 2,3 = n-tile 2j+1
#pragma unroll
            for (int j = 0; j < 4; j++) {
                unsigned bd = su32(&Bs[ks + (lane & 7) + ((lane >> 3) & 1) * 8]
                                      [wn * 64 + j * 16 + (lane >> 4) * 8]);
                ldsm_x4_t(bf[j], bd);
            }
#pragma unroll
            for (int mi = 0; mi < 2; mi++)
#pragma unroll
                for (int j = 0; j < 4; j++) {
                    mma16816(acc[mi][2 * j],     af[mi], &bf[j][0]);
                    mma16816(acc[mi][2 * j + 1], af[mi], &bf[j][2]);
                }
        }
        __syncthreads();
    }

    // ---- epilogue: fp16 h store + fused as/ad ----
    int head = blockIdx.y * 2 + wn;
    int col0 = ncol0 + wn * 64;
    float2 avv[8], dvv[8];
#pragma unroll
    for (int ni = 0; ni < 8; ni++) {
        int c = col0 + ni * 8 + (lane & 3) * 2;
        avv[ni] = *(const float2*)(a_src + c);
        dvv[ni] = *(const float2*)(a_dst + c);
    }
#pragma unroll
    for (int mi = 0; mi < 2; mi++) {
#pragma unroll
        for (int hf = 0; hf < 2; hf++) {
            int row = row0 + wm * 32 + mi * 16 + hf * 8 + (lane >> 2);
            bool valid = row < N_NODES;
            float ps = 0.f, pd = 0.f;
#pragma unroll
            for (int ni = 0; ni < 8; ni++) {
                float d0 = acc[mi][ni][hf * 2], d1 = acc[mi][ni][hf * 2 + 1];
                ps += d0 * avv[ni].x + d1 * avv[ni].y;
                pd += d0 * dvv[ni].x + d1 * dvv[ni].y;
                if (valid) {
                    __half2 q = __floats2half2_rn(d0, d1);
                    *(__half2*)(g_h + (long)row * 256 + col0 + ni * 8 + (lane & 3) * 2) = q;
                }
            }
            ps += __shfl_xor_sync(0xFFFFFFFF, ps, 1);
            ps += __shfl_xor_sync(0xFFFFFFFF, ps, 2);
            pd += __shfl_xor_sync(0xFFFFFFFF, pd, 1);
            pd += __shfl_xor_sync(0xFFFFFFFF, pd, 2);
            if ((lane & 3) == 0 && valid) {
                g_as[row * HEADS + head] = ps;
                g_ad[row * HEADS + head] = pd;
            }
        }
    }
}

// ============================================================================
// GAT attention: online softmax + aggregation + head-mean + bias + relu.
// One warp per dst node.  Output fp16.
// ============================================================================
__device__ __forceinline__ float lrelu(float v) {
    return v > 0.f ? v : NEG_SLOPE * v;
}

__global__ __launch_bounds__(256) void k_gat_attn(
    const float* __restrict__ bias)
{
    int n = (blockIdx.x * blockDim.x + threadIdx.x) >> 5;
    int lane = threadIdx.x & 31;
    if (n >= N_NODES) return;

    int beg = g_rowptr[n], end = g_rowptr[n + 1];
    float4 adv = *(const float4*)(g_ad + n * 4);
    float ad0 = adv.x, ad1 = adv.y, ad2 = adv.z, ad3 = adv.w;

    // online (max, rescaled sum) per head
    float mx0 = -1e30f, mx1 = -1e30f, mx2 = -1e30f, mx3 = -1e30f;
    float se0 = 0.f, se1 = 0.f, se2 = 0.f, se3 = 0.f;
    for (int e = beg + lane; e < end; e += 32) {
        int s = g_col[e];
        float4 av = *(const float4*)(g_as + s * 4);
        float e0 = lrelu(av.x + ad0), e1 = lrelu(av.y + ad1);
        float e2 = lrelu(av.z + ad2), e3 = lrelu(av.w + ad3);
        float m;
        m = fmaxf(mx0, e0); se0 = se0 * __expf(mx0 - m) + __expf(e0 - m); mx0 = m;
        m = fmaxf(mx1, e1); se1 = se1 * __expf(mx1 - m) + __expf(e1 - m); mx1 = m;
        m = fmaxf(mx2, e2); se2 = se2 * __expf(mx2 - m) + __expf(e2 - m); mx2 = m;
        m = fmaxf(mx3, e3); se3 = se3 * __expf(mx3 - m) + __expf(e3 - m); mx3 = m;
    }
#pragma unroll
    for (int off = 16; off >= 1; off >>= 1) {
        float m2, s2, mm;
        m2 = __shfl_xor_sync(0xFFFFFFFF, mx0, off); s2 = __shfl_xor_sync(0xFFFFFFFF, se0, off);
        mm = fmaxf(mx0, m2); se0 = se0 * __expf(mx0 - mm) + s2 * __expf(m2 - mm); mx0 = mm;
        m2 = __shfl_xor_sync(0xFFFFFFFF, mx1, off); s2 = __shfl_xor_sync(0xFFFFFFFF, se1, off);
        mm = fmaxf(mx1, m2); se1 = se1 * __expf(mx1 - mm) + s2 * __expf(m2 - mm); mx1 = mm;
        m2 = __shfl_xor_sync(0xFFFFFFFF, mx2, off); s2 = __shfl_xor_sync(0xFFFFFFFF, se2, off);
        mm = fmaxf(mx2, m2); se2 = se2 * __expf(mx2 - mm) + s2 * __expf(m2 - mm); mx2 = mm;
        m2 = __shfl_xor_sync(0xFFFFFFFF, mx3, off); s2 = __shfl_xor_sync(0xFFFFFFFF, se3, off);
        mm = fmaxf(mx3, m2); se3 = se3 * __expf(mx3 - mm) + s2 * __expf(m2 - mm); mx3 = mm;
    }

    int h0 = lane >> 3;
    float myad = (h0 == 0) ? ad0 : (h0 == 1) ? ad1 : (h0 == 2) ? ad2 : ad3;
    float mymx = (h0 == 0) ? mx0 : (h0 == 1) ? mx1 : (h0 == 2) ? mx2 : mx3;
    float myinv = 1.f / ((h0 == 0) ? se0 : (h0 == 1) ? se1 : (h0 == 2) ? se2 : se3);
    int k0 = lane * 8;

    float acc[8];
#pragma unroll
    for (int k = 0; k < 8; k++) acc[k] = 0.f;

    for (int e = beg; e < end; e++) {
        int s = g_col[e];                         // uniform -> broadcast load
        float myas = g_as[s * 4 + h0];
        float alpha = __expf(lrelu(myas + myad) - mymx) * myinv;
        const __half* hp = g_h + (long)s * F1 + k0;
        uint4 raw = *(const uint4*)hp;            // 8 halves
        __half2* ph = (__half2*)&raw;
        float2 f0 = __half22float2(ph[0]);
        float2 f1 = __half22float2(ph[1]);
        float2 f2 = __half22float2(ph[2]);
        float2 f3 = __half22float2(ph[3]);
        acc[0] += alpha * f0.x; acc[1] += alpha * f0.y;
        acc[2] += alpha * f1.x; acc[3] += alpha * f1.y;
        acc[4] += alpha * f2.x; acc[5] += alpha * f2.y;
        acc[6] += alpha * f3.x; acc[7] += alpha * f3.y;
    }

#pragma unroll
    for (int k = 0; k < 8; k++) {
        acc[k] += __shfl_xor_sync(0xFFFFFFFF, acc[k], 8);
        acc[k] += __shfl_xor_sync(0xFFFFFFFF, acc[k], 16);
    }
    if (lane < 8) {
        __half* op = g_hpost + (long)n * HID + lane * 8;
        __half2 q[4];
#pragma unroll
        for (int k = 0; k < 4; k++) {
            float v0 = acc[2 * k]     * 0.25f + bias[lane * 8 + 2 * k];
            float v1 = acc[2 * k + 1] * 0.25f + bias[lane * 8 + 2 * k + 1];
            v0 = v0 > 0.f ? v0 : 0.f;
            v1 = v1 > 0.f ? v1 : 0.f;
            q[k] = __floats2half2_rn(v0, v1);
        }
        *(uint4*)op = *(uint4*)q;
    }
}

// ============================================================================
// pool (segment mean over sorted batch) + FC  (one block per graph, 64 thr)
// ============================================================================
__device__ __forceinline__ int lowerb(const int* b, int n, int v) {
    int lo = 0, hi = n;
    while (lo < hi) {
        int m = (lo + hi) >> 1;
        if (b[m] < v) lo = m + 1; else hi = m;
    }
    return lo;
}

__global__ __launch_bounds__(64) void k_pool_fc(
    const int* __restrict__ batch,
    const float* __restrict__ fcW, const float* __restrict__ fcb,
    float* __restrict__ out)
{
    int g = blockIdx.x;
    int d = threadIdx.x;
    int lo = lowerb(batch, N_NODES, g);
    int hi = lowerb(batch, N_NODES, g + 1);
    float acc = 0.f;
    for (int i = lo; i < hi; i++) acc += __half2float(g_hpost[(long)i * HID + d]);
    int cnt = hi - lo;
    float inv = 1.f / (float)(cnt > 0 ? cnt : 1);
    __shared__ float sp[HID];
    sp[d] = acc * inv;
    __syncthreads();
    if (d < OUT_DIM) {
        float o = fcb[d];
#pragma unroll
        for (int k = 0; k < HID; k++) o += sp[k] * fcW[k * OUT_DIM + d];
        out[g * OUT_DIM + d] = o;
    }
}

// ============================================================================
// launcher — kernel launches ONLY (graph-capture safe)
// ============================================================================
extern "C" void kernel_launch(void* const* d_in, const int* in_sizes, int n_in,
                              void* d_out, int out_size)
{
    const float* x     = (const float*)d_in[0];
    const int*   ei    = (const int*)d_in[1];     // int32 (JAX x64 disabled)
    const int*   batch = (const int*)d_in[2];     // int32
    const float* W1    = (const float*)d_in[3];
    const float* a1s   = (const float*)d_in[4];
    const float* a1d   = (const float*)d_in[5];
    const float* b1    = (const float*)d_in[6];
    const float* W2    = (const float*)d_in[7];
    const float* a2s   = (const float*)d_in[8];
    const float* a2d   = (const float*)d_in[9];
    const float* b2    = (const float*)d_in[10];
    const float* fcW   = (const float*)d_in[11];
    const float* fcb   = (const float*)d_in[12];
    float*       out   = (float*)d_out;

    const int NCH = (N_NODES + 1023) / 1024;   // 49
    dim3 ggrid((N_NODES + 127) / 128, 2);      // 391 x 2

    // positions 1-3
    k_cvt_x<<<(N_NODES * IN_DIM / 4 + 255) / 256, 256>>>(x);
    k_cvt_w<<<(IN_DIM * F1 + HID * F1 + 255) / 256, 256>>>(W1, W2);
    k_zero_count<<<(N_NODES + 255) / 256, 256>>>();
    // position 4: big GEMM — lands in the ncu capture window
    k_gemm_hmma<IN_DIM, true><<<ggrid, 256>>>(a1s, a1d);
    // CSR build
    k_hist<<<(E_TOT + 255) / 256, 256>>>(ei);
    k_scan1<<<NCH, 1024>>>();
    k_scan2<<<1, 64>>>(NCH);
    k_scan3<<<NCH, 1024>>>();
    k_cursor_init<<<(N_NODES + 255) / 256, 256>>>();
    k_scatter<<<(E_TOT + 255) / 256, 256>>>(ei);

    // layer 1 attention
    k_gat_attn<<<(N_NODES + 7) / 8, 256>>>(b1);

    // layer 2
    k_gemm_hmma<HID, false><<<ggrid, 256>>>(a2s, a2d);
    k_gat_attn<<<(N_NODES + 7) / 8, 256>>>(b2);

    // pool + fc
    k_pool_fc<<<N_GRAPHS, 64>>>(batch, fcW, fcb, out);
}

// round 7
// speedup vs baseline: 1.6065x; 1.0493x over previous
#include <cuda_runtime.h>
#include <cuda_fp16.h>
#include <math.h>

#define N_NODES 50000
#define N_EDGES 800000
#define E_TOT   850000          // edges + self loops
#define IN_DIM  128
#define HID     64
#define HEADS   4
#define F1      256             // HEADS*HID
#define OUT_DIM 16
#define N_GRAPHS 500
#define NEG_SLOPE 0.2f

// ---------------- device scratch (static, no runtime alloc) ----------------
__device__ __align__(16) __half g_xh[N_NODES * IN_DIM];   // x in fp16
__device__ __align__(16) __half g_w1h[IN_DIM * F1];       // W1 fp16
__device__ __align__(16) __half g_w2h[HID * F1];          // W2 fp16
__device__ __align__(16) __half g_h[N_NODES * F1];        // post-GEMM features, fp16
__device__ __align__(16) __half g_hpost[N_NODES * HID];   // post-attention, fp16
__device__ __align__(16) float g_as[N_NODES * HEADS];
__device__ __align__(16) float g_ad[N_NODES * HEADS];
__device__ int   g_count[N_NODES];
__device__ int   g_rowptr[N_NODES + 1];
__device__ int   g_cursor[N_NODES];
__device__ int   g_col[E_TOT];
__device__ int   g_chunksum[64];
__device__ int   g_chunkoff[64];

// ---------------- mma / cp.async helpers ----------------
__device__ __forceinline__ unsigned su32(const void* p) {
    return (unsigned)__cvta_generic_to_shared(p);
}
__device__ __forceinline__ void ldsm_x4(unsigned* r, unsigned addr) {
    asm volatile("ldmatrix.sync.aligned.m8n8.x4.shared.b16 {%0,%1,%2,%3}, [%4];"
        : "=r"(r[0]), "=r"(r[1]), "=r"(r[2]), "=r"(r[3]) : "r"(addr));
}
__device__ __forceinline__ void ldsm_x4_t(unsigned* r, unsigned addr) {
    asm volatile("ldmatrix.sync.aligned.m8n8.x4.trans.shared.b16 {%0,%1,%2,%3}, [%4];"
        : "=r"(r[0]), "=r"(r[1]), "=r"(r[2]), "=r"(r[3]) : "r"(addr));
}
__device__ __forceinline__ void mma16816(float* d, const unsigned* a, const unsigned* b) {
    asm volatile("mma.sync.aligned.m16n8k16.row.col.f32.f16.f16.f32 "
        "{%0,%1,%2,%3}, {%4,%5,%6,%7}, {%8,%9}, {%0,%1,%2,%3};"
        : "+f"(d[0]), "+f"(d[1]), "+f"(d[2]), "+f"(d[3])
        : "r"(a[0]), "r"(a[1]), "r"(a[2]), "r"(a[3]), "r"(b[0]), "r"(b[1]));
}
__device__ __forceinline__ void cp16(unsigned dst, const void* src) {
    asm volatile("cp.async.cg.shared.global [%0], [%1], 16;" :: "r"(dst), "l"(src));
}

// ============================================================================
// fp32 -> fp16 conversions (+ fused g_count zeroing)
// ============================================================================
__global__ void k_cvt_x(const float* __restrict__ x) {
    int i = blockIdx.x * blockDim.x + threadIdx.x;   // float4 index
    const int total = N_NODES * IN_DIM / 4;
    if (i < N_NODES) g_count[i] = 0;                 // fused zero_count
    if (i >= total) return;
    float4 v = *(const float4*)(x + (long)i * 4);
    __half2 h0 = __floats2half2_rn(v.x, v.y);
    __half2 h1 = __floats2half2_rn(v.z, v.w);
    __half2* p = (__half2*)(g_xh + (long)i * 4);
    p[0] = h0; p[1] = h1;
}

__global__ void k_cvt_w(const float* __restrict__ W1, const float* __restrict__ W2) {
    int i = blockIdx.x * blockDim.x + threadIdx.x;
    const int n1 = IN_DIM * F1;         // 32768
    const int n2 = HID * F1;            // 16384
    if (i < n1) g_w1h[i] = __float2half_rn(W1[i]);
    else if (i < n1 + n2) g_w2h[i - n1] = __float2half_rn(W2[i - n1]);
}

// ============================================================================
// CSR build  (edge_index is int32: row 0 = src, row 1 = dst)
// ============================================================================
__global__ void k_hist(const int* __restrict__ ei) {
    int e = blockIdx.x * blockDim.x + threadIdx.x;
    if (e >= E_TOT) return;
    int dst = (e < N_EDGES) ? ei[N_EDGES + e] : (e - N_EDGES);
    atomicAdd(&g_count[dst], 1);
}

__global__ void k_scan1() {
    __shared__ int sh[1024];
    int tid = threadIdx.x;
    int i = blockIdx.x * 1024 + tid;
    int v = (i < N_NODES) ? g_count[i] : 0;
    sh[tid] = v;
    __syncthreads();
#pragma unroll
    for (int off = 1; off < 1024; off <<= 1) {
        int t = (tid >= off) ? sh[tid - off] : 0;
        __syncthreads();
        sh[tid] += t;
        __syncthreads();
    }
    if (i < N_NODES) g_rowptr[i + 1] = sh[tid];
    if (tid == 1023) g_chunksum[blockIdx.x] = sh[1023];
}

__global__ void k_scan2(int nch) {
    __shared__ int s[64];
    int tid = threadIdx.x;
    int v = (tid < nch) ? g_chunksum[tid] : 0;
    s[tid] = v;
    __syncthreads();
#pragma unroll
    for (int off = 1; off < 64; off <<= 1) {
        int t = (tid >= off) ? s[tid - off] : 0;
        __syncthreads();
        s[tid] += t;
        __syncthreads();
    }
    if (tid < nch) g_chunkoff[tid] = s[tid] - v;
}

// scan finalize + cursor init fused
__global__ void k_scan3() {
    int tid = threadIdx.x;
    int i = blockIdx.x * 1024 + tid;
    if (i < N_NODES) {
        int v = g_rowptr[i + 1] + g_chunkoff[blockIdx.x];
        g_rowptr[i + 1] = v;
        if (i + 1 < N_NODES) g_cursor[i + 1] = v;
    }
    if (blockIdx.x == 0 && tid == 0) {
        g_rowptr[0] = 0;
        g_cursor[0] = 0;
    }
}

__global__ void k_scatter(const int* __restrict__ ei) {
    int e = blockIdx.x * blockDim.x + threadIdx.x;
    if (e >= E_TOT) return;
    int src, dst;
    if (e < N_EDGES) {
        src = ei[e];
        dst = ei[N_EDGES + e];
    } else {
        src = dst = e - N_EDGES;
    }
    int p = atomicAdd(&g_cursor[dst], 1);
    g_col[p] = src;
}

// ============================================================================
// HMMA GEMM: g_h[M,256](fp16) = A[M,K](fp16) @ W[K,256](fp16), fp32 acc.
// cp.async double-buffered, 2 blocks/SM. Fused as/ad epilogue.
// BM=128, BN=128 (grid.y=2), BK=32. 256 threads = 8 warps (4x2), warp=32x64.
// ============================================================================
#define SA 40    // As row stride (halves)
#define SB 136   // Bs row stride (halves)

template <int K, bool USE_X>
__global__ __launch_bounds__(256, 2) void k_gemm_hmma(
    const float* __restrict__ a_src, const float* __restrict__ a_dst)
{
    constexpr int NC = K / 32;           // k-chunks
    __shared__ __half As[2][128][SA];    // 20.5 KB
    __shared__ __half Bs[2][32][SB];     // 17.4 KB

    const __half* A = USE_X ? g_xh : g_hpost;
    const __half* W = USE_X ? g_w1h : g_w2h;

    int tid = threadIdx.x;
    int lane = tid & 31, wid = tid >> 5;
    int wm = wid >> 1, wn = wid & 1;
    int row0 = blockIdx.x * 128;
    int ncol0 = blockIdx.y * 128;

    // per-thread load coords (hoisted)
    int ar = tid >> 2, ac = tid & 3;         // A: rows tid/4, col-16B tid%4 (x2 iters)
    int bk = tid >> 4, bc = tid & 15;        // B: k-row tid/16, col-16B tid%16 (x2 iters)

    float acc[2][8][4];
#pragma unroll
    for (int mi = 0; mi < 2; mi++)
#pragma unroll
        for (int ni = 0; ni < 8; ni++)
#pragma unroll
            for (int q = 0; q < 4; q++) acc[mi][ni][q] = 0.f;

    // ---- async load of one k-chunk into buffer b ----
    auto load_chunk = [&](int kc, int b) {
#pragma unroll
        for (int it = 0; it < 2; it++) {
            int r = ar + it * 64;
            int row = row0 + r;
            row = row < N_NODES ? row : N_NODES - 1;   // clamp (never stored)
            cp16(su32(&As[b][r][ac * 8]), A + (long)row * K + kc + ac * 8);
        }
#pragma unroll
        for (int it = 0; it < 2; it++) {
            int k = bk + it * 16;
            cp16(su32(&Bs[b][k][bc * 8]), W + (long)(kc + k) * 256 + ncol0 + bc * 8);
        }
        asm volatile("cp.async.commit_group;");
    };

    load_chunk(0, 0);

#pragma unroll
    for (int c = 0; c < NC; c++) {
        int b = c & 1;
        if (c + 1 < NC) {
            load_chunk((c + 1) * 32, (c + 1) & 1);
            asm volatile("cp.async.wait_group 1;");
        } else {
            asm volatile("cp.async.wait_group 0;");
        }
        __syncthreads();

#pragma unroll
        for (int ks = 0; ks < 32; ks += 16) {
            unsigned af[2][4];
#pragma unroll
            for (int mi = 0; mi < 2; mi++) {
                unsigned ad = su32(&As[b][wm * 32 + mi * 16 + (lane & 15)][ks + (lane >> 4) * 8]);
                ldsm_x4(af[mi], ad);
            }
            unsigned bf[4][4];
#pragma unroll
            for (int j = 0; j < 4; j++) {
                unsigned bd = su32(&Bs[b][ks + (lane & 7) + ((lane >> 3) & 1) * 8]
                                        [wn * 64 + j * 16 + (lane >> 4) * 8]);
                ldsm_x4_t(bf[j], bd);
            }
#pragma unroll
            for (int mi = 0; mi < 2; mi++)
#pragma unroll
                for (int j = 0; j < 4; j++) {
                    mma16816(acc[mi][2 * j],     af[mi], &bf[j][0]);
                    mma16816(acc[mi][2 * j + 1], af[mi], &bf[j][2]);
                }
        }
        __syncthreads();
    }

    // ---- epilogue: fp16 h store + fused as/ad ----
    int head = blockIdx.y * 2 + wn;
    int col0 = ncol0 + wn * 64;
    float2 avv[8], dvv[8];
#pragma unroll
    for (int ni = 0; ni < 8; ni++) {
        int c = col0 + ni * 8 + (lane & 3) * 2;
        avv[ni] = *(const float2*)(a_src + c);
        dvv[ni] = *(const float2*)(a_dst + c);
    }
#pragma unroll
    for (int mi = 0; mi < 2; mi++) {
#pragma unroll
        for (int hf = 0; hf < 2; hf++) {
            int row = row0 + wm * 32 + mi * 16 + hf * 8 + (lane >> 2);
            bool valid = row < N_NODES;
            float ps = 0.f, pd = 0.f;
#pragma unroll
            for (int ni = 0; ni < 8; ni++) {
                float d0 = acc[mi][ni][hf * 2], d1 = acc[mi][ni][hf * 2 + 1];
                ps += d0 * avv[ni].x + d1 * avv[ni].y;
                pd += d0 * dvv[ni].x + d1 * dvv[ni].y;
                if (valid) {
                    __half2 q = __floats2half2_rn(d0, d1);
                    *(__half2*)(g_h + (long)row * 256 + col0 + ni * 8 + (lane & 3) * 2) = q;
                }
            }
            ps += __shfl_xor_sync(0xFFFFFFFF, ps, 1);
            ps += __shfl_xor_sync(0xFFFFFFFF, ps, 2);
            pd += __shfl_xor_sync(0xFFFFFFFF, pd, 1);
            pd += __shfl_xor_sync(0xFFFFFFFF, pd, 2);
            if ((lane & 3) == 0 && valid) {
                g_as[row * HEADS + head] = ps;
                g_ad[row * HEADS + head] = pd;
            }
        }
    }
}

// ============================================================================
// GAT attention: online softmax + aggregation (x2 unrolled) + head-mean
// + bias + relu.  One warp per dst node.  Output fp16.
// ============================================================================
__device__ __forceinline__ float lrelu(float v) {
    return v > 0.f ? v : NEG_SLOPE * v;
}

__global__ __launch_bounds__(256) void k_gat_attn(
    const float* __restrict__ bias)
{
    int n = (blockIdx.x * blockDim.x + threadIdx.x) >> 5;
    int lane = threadIdx.x & 31;
    if (n >= N_NODES) return;

    int beg = g_rowptr[n], end = g_rowptr[n + 1];
    float4 adv = *(const float4*)(g_ad + n * 4);
    float ad0 = adv.x, ad1 = adv.y, ad2 = adv.z, ad3 = adv.w;

    // online (max, rescaled sum) per head
    float mx0 = -1e30f, mx1 = -1e30f, mx2 = -1e30f, mx3 = -1e30f;
    float se0 = 0.f, se1 = 0.f, se2 = 0.f, se3 = 0.f;
    for (int e = beg + lane; e < end; e += 32) {
        int s = g_col[e];
        float4 av = *(const float4*)(g_as + s * 4);
        float e0 = lrelu(av.x + ad0), e1 = lrelu(av.y + ad1);
        float e2 = lrelu(av.z + ad2), e3 = lrelu(av.w + ad3);
        float m;
        m = fmaxf(mx0, e0); se0 = se0 * __expf(mx0 - m) + __expf(e0 - m); mx0 = m;
        m = fmaxf(mx1, e1); se1 = se1 * __expf(mx1 - m) + __expf(e1 - m); mx1 = m;
        m = fmaxf(mx2, e2); se2 = se2 * __expf(mx2 - m) + __expf(e2 - m); mx2 = m;
        m = fmaxf(mx3, e3); se3 = se3 * __expf(mx3 - m) + __expf(e3 - m); mx3 = m;
    }
#pragma unroll
    for (int off = 16; off >= 1; off >>= 1) {
        float m2, s2, mm;
        m2 = __shfl_xor_sync(0xFFFFFFFF, mx0, off); s2 = __shfl_xor_sync(0xFFFFFFFF, se0, off);
        mm = fmaxf(mx0, m2); se0 = se0 * __expf(mx0 - mm) + s2 * __expf(m2 - mm); mx0 = mm;
        m2 = __shfl_xor_sync(0xFFFFFFFF, mx1, off); s2 = __shfl_xor_sync(0xFFFFFFFF, se1, off);
        mm = fmaxf(mx1, m2); se1 = se1 * __expf(mx1 - mm) + s2 * __expf(m2 - mm); mx1 = mm;
        m2 = __shfl_xor_sync(0xFFFFFFFF, mx2, off); s2 = __shfl_xor_sync(0xFFFFFFFF, se2, off);
        mm = fmaxf(mx2, m2); se2 = se2 * __expf(mx2 - mm) + s2 * __expf(m2 - mm); mx2 = mm;
        m2 = __shfl_xor_sync(0xFFFFFFFF, mx3, off); s2 = __shfl_xor_sync(0xFFFFFFFF, se3, off);
        mm = fmaxf(mx3, m2); se3 = se3 * __expf(mx3 - mm) + s2 * __expf(m2 - mm); mx3 = mm;
    }

    int h0 = lane >> 3;
    float myad = (h0 == 0) ? ad0 : (h0 == 1) ? ad1 : (h0 == 2) ? ad2 : ad3;
    float mymx = (h0 == 0) ? mx0 : (h0 == 1) ? mx1 : (h0 == 2) ? mx2 : mx3;
    float myinv = 1.f / ((h0 == 0) ? se0 : (h0 == 1) ? se1 : (h0 == 2) ? se2 : se3);
    int k0 = lane * 8;

    float acc[8];
#pragma unroll
    for (int k = 0; k < 8; k++) acc[k] = 0.f;

    // aggregation, unrolled x2 for MLP
    int e = beg;
    for (; e + 2 <= end; e += 2) {
        int s0 = g_col[e], s1 = g_col[e + 1];
        float as0 = g_as[s0 * 4 + h0];
        float as1 = g_as[s1 * 4 + h0];
        uint4 raw0 = *(const uint4*)(g_h + (long)s0 * F1 + k0);
        uint4 raw1 = *(const uint4*)(g_h + (long)s1 * F1 + k0);
        float al0 = __expf(lrelu(as0 + myad) - mymx) * myinv;
        float al1 = __expf(lrelu(as1 + myad) - mymx) * myinv;
        __half2* p0 = (__half2*)&raw0;
        __half2* p1 = (__half2*)&raw1;
#pragma unroll
        for (int q = 0; q < 4; q++) {
            float2 f0 = __half22float2(p0[q]);
            float2 f1 = __half22float2(p1[q]);
            acc[2 * q]     += al0 * f0.x + al1 * f1.x;
            acc[2 * q + 1] += al0 * f0.y + al1 * f1.y;
        }
    }
    if (e < end) {
        int s = g_col[e];
        float myas = g_as[s * 4 + h0];
        float alpha = __expf(lrelu(myas + myad) - mymx) * myinv;
        uint4 raw = *(const uint4*)(g_h + (long)s * F1 + k0);
        __half2* ph = (__half2*)&raw;
#pragma unroll
        for (int q = 0; q < 4; q++) {
            float2 f = __half22float2(ph[q]);
            acc[2 * q]     += alpha * f.x;
            acc[2 * q + 1] += alpha * f.y;
        }
    }

    // head mean across the 4 head-groups of lanes
#pragma unroll
    for (int k = 0; k < 8; k++) {
        acc[k] += __shfl_xor_sync(0xFFFFFFFF, acc[k], 8);
        acc[k] += __shfl_xor_sync(0xFFFFFFFF, acc[k], 16);
    }
    if (lane < 8) {
        __half* op = g_hpost + (long)n * HID + lane * 8;
        __half2 q[4];
#pragma unroll
        for (int k = 0; k < 4; k++) {
            float v0 = acc[2 * k]     * 0.25f + bias[lane * 8 + 2 * k];
            float v1 = acc[2 * k + 1] * 0.25f + bias[lane * 8 + 2 * k + 1];
            v0 = v0 > 0.f ? v0 : 0.f;
            v1 = v1 > 0.f ? v1 : 0.f;
            q[k] = __floats2half2_rn(v0, v1);
        }
        *(uint4*)op = *(uint4*)q;
    }
}

// ============================================================================
// pool (segment mean over sorted batch) + FC  (one block per graph, 64 thr)
// ============================================================================
__device__ __forceinline__ int lowerb(const int* b, int n, int v) {
    int lo = 0, hi = n;
    while (lo < hi) {
        int m = (lo + hi) >> 1;
        if (b[m] < v) lo = m + 1; else hi = m;
    }
    return lo;
}

__global__ __launch_bounds__(64) void k_pool_fc(
    const int* __restrict__ batch,
    const float* __restrict__ fcW, const float* __restrict__ fcb,
    float* __restrict__ out)
{
    int g = blockIdx.x;
    int d = threadIdx.x;
    int lo = lowerb(batch, N_NODES, g);
    int hi = lowerb(batch, N_NODES, g + 1);
    float acc = 0.f;
    for (int i = lo; i < hi; i++) acc += __half2float(g_hpost[(long)i * HID + d]);
    int cnt = hi - lo;
    float inv = 1.f / (float)(cnt > 0 ? cnt : 1);
    __shared__ float sp[HID];
    sp[d] = acc * inv;
    __syncthreads();
    if (d < OUT_DIM) {
        float o = fcb[d];
#pragma unroll
        for (int k = 0; k < HID; k++) o += sp[k] * fcW[k * OUT_DIM + d];
        out[g * OUT_DIM + d] = o;
    }
}

// ============================================================================
// launcher — kernel launches ONLY (graph-capture safe)
// ============================================================================
extern "C" void kernel_launch(void* const* d_in, const int* in_sizes, int n_in,
                              void* d_out, int out_size)
{
    const float* x     = (const float*)d_in[0];
    const int*   ei    = (const int*)d_in[1];     // int32 (JAX x64 disabled)
    const int*   batch = (const int*)d_in[2];     // int32
    const float* W1    = (const float*)d_in[3];
    const float* a1s   = (const float*)d_in[4];
    const float* a1d   = (const float*)d_in[5];
    const float* b1    = (const float*)d_in[6];
    const float* W2    = (const float*)d_in[7];
    const float* a2s   = (const float*)d_in[8];
    const float* a2d   = (const float*)d_in[9];
    const float* b2    = (const float*)d_in[10];
    const float* fcW   = (const float*)d_in[11];
    const float* fcb   = (const float*)d_in[12];
    float*       out   = (float*)d_out;

    const int NCH = (N_NODES + 1023) / 1024;   // 49
    dim3 ggrid((N_NODES + 127) / 128, 2);      // 391 x 2

    // conversions (+ fused count zeroing), then big GEMM at position 4-ish
    k_cvt_x<<<(N_NODES * IN_DIM / 4 + 255) / 256, 256>>>(x);
    k_cvt_w<<<(IN_DIM * F1 + HID * F1 + 255) / 256, 256>>>(W1, W2);
    k_hist<<<(E_TOT + 255) / 256, 256>>>(ei);
    k_gemm_hmma<IN_DIM, true><<<ggrid, 256>>>(a1s, a1d);
    // CSR back half
    k_scan1<<<NCH, 1024>>>();
    k_scan2<<<1, 64>>>(NCH);
    k_scan3<<<NCH, 1024>>>();
    k_scatter<<<(E_TOT + 255) / 256, 256>>>(ei);

    // layer 1 attention
    k_gat_attn<<<(N_NODES + 7) / 8, 256>>>(b1);

    // layer 2
    k_gemm_hmma<HID, false><<<ggrid, 256>>>(a2s, a2d);
    k_gat_attn<<<(N_NODES + 7) / 8, 256>>>(b2);

    // pool + fc
    k_pool_fc<<<N_GRAPHS, 64>>>(batch, fcW, fcb, out);
}